// round 5
// baseline (speedup 1.0000x reference)
#include <cuda_runtime.h>
#include <cuda_fp16.h>
#include <math.h>
#include <stdint.h>

#define B_ROWS 65536
#define T_DIM  365

// ---------------------------------------------------------------------------
// Scratch (device globals)
// ---------------------------------------------------------------------------
__device__ half g_x  [(size_t)B_ROWS * 384];
__device__ half g_h1 [(size_t)B_ROWS * 512];
__device__ half g_h2 [(size_t)B_ROWS * 256];
__device__ half g_cb [(size_t)B_ROWS * 192];   // [h3(128) | stats(32) | zero(32)]
__device__ half g_c1 [(size_t)B_ROWS * 64];
__device__ float g_c2[(size_t)B_ROWS * 32];
// weights transposed to [N, Kpad] fp16
__device__ half g_w1[512*384];
__device__ half g_w2[256*512];
__device__ half g_w3[128*256];
__device__ half g_w4[64*192];
__device__ half g_w5[32*64];

// ---------------------------------------------------------------------------
// Baseline-PTX helpers (sm_80+; assemble on plain sm_103)
// ---------------------------------------------------------------------------
__device__ __forceinline__ uint32_t smem_u32(const void* p) {
    uint32_t a;
    asm("{ .reg .u64 t; cvta.to.shared.u64 t, %1; cvt.u32.u64 %0, t; }" : "=r"(a) : "l"(p));
    return a;
}
__device__ __forceinline__ void cpa16(uint32_t dst, const void* src) {
    asm volatile("cp.async.cg.shared.global [%0], [%1], 16;" :: "r"(dst), "l"(src));
}
#define CP_COMMIT() asm volatile("cp.async.commit_group;" ::: "memory")
template<int N>
__device__ __forceinline__ void cp_wait() {
    asm volatile("cp.async.wait_group %0;" :: "n"(N) : "memory");
}
#define LDM4(r, addr) \
    asm volatile("ldmatrix.sync.aligned.m8n8.x4.shared.b16 {%0,%1,%2,%3}, [%4];" \
        : "=r"((r)[0]), "=r"((r)[1]), "=r"((r)[2]), "=r"((r)[3]) : "r"(addr))
#define MMA_F16(d, a, b0, b1) \
    asm volatile("mma.sync.aligned.m16n8k16.row.col.f32.f16.f16.f32 " \
        "{%0,%1,%2,%3}, {%4,%5,%6,%7}, {%8,%9}, {%0,%1,%2,%3};" \
        : "+f"((d)[0]), "+f"((d)[1]), "+f"((d)[2]), "+f"((d)[3]) \
        : "r"((a)[0]), "r"((a)[1]), "r"((a)[2]), "r"((a)[3]), \
          "r"(b0), "r"(b1))

// ---------------------------------------------------------------------------
// fp16 mma.sync GEMM: out[128 x NT] = relu(A @ W^T + bias)
// A: [B, KPAD] fp16; W: [N, KPAD] fp16 (pre-transposed). fp32 reg accum.
// k-chunk 64 (128B rows, 8x16B granules, XOR-(r&7) swizzle).
// 3-stage cp.async pipeline; 8 warps = 4m x 2n (warp tile 32 x NT/2).
// ---------------------------------------------------------------------------
template<int NT, int NC, int OCC, bool FP32_OUT>
__global__ void __launch_bounds__(256, OCC)
gemm_mma(const half* __restrict__ A, const half* __restrict__ W,
         const float* __restrict__ bias,
         half* __restrict__ Oh, float* __restrict__ Of, int ldc)
{
    constexpr int KPAD   = NC * 64;
    constexpr int WN     = NT / 2;          // warp n-extent
    constexpr int NB     = WN / 16;         // B ldmatrix.x4 per k16
    constexpr int NF     = WN / 8;          // n8 frags per warp
    constexpr int ABYTES = 128 * 128;
    constexpr int BBYTES = NT * 128;
    constexpr int STAGE  = ABYTES + BBYTES;

    extern __shared__ __align__(1024) char sm[];
    const uint32_t sb = smem_u32(sm);

    const int tid  = threadIdx.x;
    const int wid  = tid >> 5;
    const int lane = tid & 31;
    const int m0   = blockIdx.y * 128;
    const int n0   = blockIdx.x * NT;
    const int wm   = (wid >> 1) * 32;
    const int wn   = (wid & 1) * WN;

    float acc[2][NF][4];
    #pragma unroll
    for (int i = 0; i < 2; i++)
        #pragma unroll
        for (int j = 0; j < NF; j++)
            #pragma unroll
            for (int q = 0; q < 4; q++) acc[i][j][q] = 0.0f;

    auto stage = [&](int c) {
        const uint32_t sA = sb + (c % 3) * STAGE;
        const uint32_t sB = sA + ABYTES;
        #pragma unroll
        for (int i = tid; i < 1024; i += 256) {          // A: 128 rows x 8 granules
            int r = i >> 3, cc = i & 7;
            cpa16(sA + r * 128 + ((cc ^ (r & 7)) << 4),
                  A + (size_t)(m0 + r) * KPAD + c * 64 + cc * 8);
        }
        #pragma unroll
        for (int i = tid; i < NT * 8; i += 256) {        // B: NT rows x 8 granules
            int r = i >> 3, cc = i & 7;
            cpa16(sB + r * 128 + ((cc ^ (r & 7)) << 4),
                  W + (size_t)(n0 + r) * KPAD + c * 64 + cc * 8);
        }
        CP_COMMIT();
    };

    stage(0);
    if (NC > 1) stage(1);

    for (int c = 0; c < NC; ++c) {
        if (c + 2 < NC)      { stage(c + 2); cp_wait<2>(); }
        else if (c + 1 < NC) { cp_wait<1>(); }
        else                 { cp_wait<0>(); }
        __syncthreads();

        const uint32_t sA = sb + (c % 3) * STAGE;
        const uint32_t sB = sA + ABYTES;

        #pragma unroll
        for (int ks = 0; ks < 4; ++ks) {                 // four k16 steps per chunk
            const int g = ks * 2 + (lane >> 4);
            uint32_t a[2][4];
            #pragma unroll
            for (int mi = 0; mi < 2; ++mi) {
                int row = wm + mi * 16 + (lane & 15);
                LDM4(a[mi], sA + row * 128 + ((g ^ (row & 7)) << 4));
            }
            #pragma unroll
            for (int nb = 0; nb < NB; ++nb) {            // load B frag, use immediately
                int row = wn + nb * 16 + (lane & 15);
                uint32_t t[4];
                LDM4(t, sB + row * 128 + ((g ^ (row & 7)) << 4));
                #pragma unroll
                for (int mi = 0; mi < 2; ++mi) {
                    MMA_F16(acc[mi][2*nb],   a[mi], t[0], t[2]);
                    MMA_F16(acc[mi][2*nb+1], a[mi], t[1], t[3]);
                }
            }
        }
        __syncthreads();
    }

    // ---- epilogue: bias + relu, store fp16 (or fp32 for last layer) ----
    #pragma unroll
    for (int mi = 0; mi < 2; ++mi) {
        #pragma unroll
        for (int nf = 0; nf < NF; ++nf) {
            int r0 = m0 + wm + mi * 16 + (lane >> 2);
            int cb = n0 + wn + nf * 8 + (lane & 3) * 2;
            float bia0 = bias[cb], bia1 = bias[cb + 1];
            #pragma unroll
            for (int h = 0; h < 2; ++h) {
                int r = r0 + h * 8;
                float v0 = fmaxf(acc[mi][nf][h * 2]     + bia0, 0.0f);
                float v1 = fmaxf(acc[mi][nf][h * 2 + 1] + bia1, 0.0f);
                if (FP32_OUT) {
                    float2 vv; vv.x = v0; vv.y = v1;
                    *(float2*)(Of + (size_t)r * ldc + cb) = vv;
                } else {
                    *(__half2*)(Oh + (size_t)r * ldc + cb) = __floats2half2_rn(v0, v1);
                }
            }
        }
    }
}

// ---------------------------------------------------------------------------
// Fused: x -> fp16 (padded to 384) + per-row stats + 6->32 projection.
// ---------------------------------------------------------------------------
__global__ void conv_stats(const float* __restrict__ x,
                           const float* __restrict__ Ws,
                           const float* __restrict__ bs,
                           half* __restrict__ xh, half* __restrict__ cb)
{
    int gwarp = (blockIdx.x * blockDim.x + threadIdx.x) >> 5;
    int lane  = threadIdx.x & 31;
    if (gwarp >= B_ROWS) return;

    const float* row = x + (size_t)gwarp * T_DIM;
    constexpr int NV = 12;
    float v[NV];
    float sum = 0.0f, mn = INFINITY, mx = -INFINITY;
    #pragma unroll
    for (int i = 0; i < NV; i++) {
        int k = lane + 32 * i;
        float t = (k < T_DIM) ? row[k] : 0.0f;
        v[i] = t;
        if (k < T_DIM) { sum += t; mn = fminf(mn, t); mx = fmaxf(mx, t); }
    }
    half* xr = xh + (size_t)gwarp * 384;
    #pragma unroll
    for (int i = 0; i < NV; i++) xr[lane + 32 * i] = __float2half_rn(v[i]);

    #pragma unroll
    for (int off = 16; off; off >>= 1) {
        sum += __shfl_xor_sync(0xffffffffu, sum, off);
        mn   = fminf(mn, __shfl_xor_sync(0xffffffffu, mn, off));
        mx   = fmaxf(mx, __shfl_xor_sync(0xffffffffu, mx, off));
    }
    float mean = sum / (float)T_DIM;
    float s2 = 0.0f, s3 = 0.0f, s4 = 0.0f;
    #pragma unroll
    for (int i = 0; i < NV; i++) {
        int k = lane + 32 * i;
        if (k < T_DIM) {
            float c  = v[i] - mean;
            float c2 = c * c;
            s2 += c2; s3 += c2 * c; s4 += c2 * c2;
        }
    }
    #pragma unroll
    for (int off = 16; off; off >>= 1) {
        s2 += __shfl_xor_sync(0xffffffffu, s2, off);
        s3 += __shfl_xor_sync(0xffffffffu, s3, off);
        s4 += __shfl_xor_sync(0xffffffffu, s4, off);
    }
    float var  = s2 / (float)(T_DIM - 1);
    float sd   = sqrtf(var);
    float skew = (s3 / (float)T_DIM) / (sd * sd * sd + 1e-8f);
    float kurt = (s4 / (float)T_DIM) / (var * var + 1e-8f);

    float st[6] = { mean, sd, mn, mx, skew, kurt };
    float o = bs[lane];
    #pragma unroll
    for (int i = 0; i < 6; i++) o = fmaf(st[i], Ws[i * 32 + lane], o);

    size_t base = (size_t)gwarp * 192;
    cb[base + 128 + lane] = __float2half_rn(o);
    cb[base + 160 + lane] = __float2half_rn(0.0f);
}

// W [K,N] fp32 -> Wt [N,Kpad] fp16 (transposed + zero-padded)
__device__ __forceinline__ void conv_one(const float* W, int K, int N, int Kpad,
                                         half* o, int i) {
    int n = i / Kpad, kp = i % Kpad;
    o[i] = __float2half_rn((kp < K) ? W[(size_t)kp * N + n] : 0.0f);
}
__global__ void conv_w_single(const float* __restrict__ W, int K, int N, int Kpad,
                              half* __restrict__ o) {
    int i = blockIdx.x * blockDim.x + threadIdx.x;
    if (i < N * Kpad) conv_one(W, K, N, Kpad, o, i);
}
// W3 + Wc1 + Wc2 in one kernel (fills a launch slot, cuts overhead)
__global__ void conv_w_rest(const float* __restrict__ W3,  half* __restrict__ w3,
                            const float* __restrict__ Wc1, half* __restrict__ w4,
                            const float* __restrict__ Wc2, half* __restrict__ w5) {
    int i = blockIdx.x * blockDim.x + threadIdx.x;
    if (i < 128 * 256)                 conv_one(W3, 256, 128, 256, w3, i);
    else if (i < 128*256 + 64*192)     conv_one(Wc1, 160, 64, 192, w4, i - 128*256);
    else if (i < 128*256 + 64*192 + 32*64)
                                       conv_one(Wc2, 64, 32, 64, w5, i - 128*256 - 64*192);
}

// ---------------------------------------------------------------------------
// Final head: out = sigmoid(c2 @ Wc3 + bc3) * 4 + 6
// ---------------------------------------------------------------------------
__global__ void head_final(const float* __restrict__ c2,
                           const float* __restrict__ Wc3,
                           const float* __restrict__ bc3,
                           float* __restrict__ out)
{
    int gwarp = (blockIdx.x * blockDim.x + threadIdx.x) >> 5;
    int lane  = threadIdx.x & 31;
    if (gwarp >= B_ROWS) return;
    float v = c2[(size_t)gwarp * 32 + lane] * Wc3[lane];
    #pragma unroll
    for (int off = 16; off; off >>= 1) v += __shfl_xor_sync(0xffffffffu, v, off);
    if (lane == 0) {
        float z = v + bc3[0];
        out[gwarp] = 4.0f / (1.0f + expf(-z)) + 6.0f;
    }
}

// ---------------------------------------------------------------------------
// Launch  (index 4 = gemm1: ncu -s 5 profiles 0-based launch #4)
// ---------------------------------------------------------------------------
extern "C" void kernel_launch(void* const* d_in, const int* in_sizes, int n_in,
                              void* d_out, int out_size)
{
    const float* x   = (const float*)d_in[0];
    const float* W1  = (const float*)d_in[1];
    const float* b1  = (const float*)d_in[2];
    const float* W2  = (const float*)d_in[3];
    const float* b2  = (const float*)d_in[4];
    const float* W3  = (const float*)d_in[5];
    const float* b3  = (const float*)d_in[6];
    const float* Ws  = (const float*)d_in[7];
    const float* bs  = (const float*)d_in[8];
    const float* Wc1 = (const float*)d_in[9];
    const float* bc1 = (const float*)d_in[10];
    const float* Wc2 = (const float*)d_in[11];
    const float* bc2 = (const float*)d_in[12];
    const float* Wc3 = (const float*)d_in[13];
    const float* bc3 = (const float*)d_in[14];
    float* out = (float*)d_out;

    half *xh, *h1, *h2, *cb, *c1, *w1, *w2, *w3, *w4, *w5;
    float* c2;
    cudaGetSymbolAddress((void**)&xh, g_x);
    cudaGetSymbolAddress((void**)&h1, g_h1);
    cudaGetSymbolAddress((void**)&h2, g_h2);
    cudaGetSymbolAddress((void**)&cb, g_cb);
    cudaGetSymbolAddress((void**)&c1, g_c1);
    cudaGetSymbolAddress((void**)&c2, g_c2);
    cudaGetSymbolAddress((void**)&w1, g_w1);
    cudaGetSymbolAddress((void**)&w2, g_w2);
    cudaGetSymbolAddress((void**)&w3, g_w3);
    cudaGetSymbolAddress((void**)&w4, g_w4);
    cudaGetSymbolAddress((void**)&w5, g_w5);

    // 3 stages x (A 16KB + B NT*128B)
    const int SM256 = 3 * (16384 + 256 * 128);  // 147456
    const int SM128 = 3 * (16384 + 128 * 128);  // 98304
    const int SM64  = 3 * (16384 + 64  * 128);  // 73728
    const int SM32  = 3 * (16384 + 32  * 128);  // 61440
    cudaFuncSetAttribute(gemm_mma<256, 6, 1, false>, cudaFuncAttributeMaxDynamicSharedMemorySize, SM256);
    cudaFuncSetAttribute(gemm_mma<256, 8, 1, false>, cudaFuncAttributeMaxDynamicSharedMemorySize, SM256);
    cudaFuncSetAttribute(gemm_mma<128, 4, 2, false>, cudaFuncAttributeMaxDynamicSharedMemorySize, SM128);
    cudaFuncSetAttribute(gemm_mma<64,  3, 2, false>, cudaFuncAttributeMaxDynamicSharedMemorySize, SM64);
    cudaFuncSetAttribute(gemm_mma<32,  1, 2, true >, cudaFuncAttributeMaxDynamicSharedMemorySize, SM32);

    // #0: fused x-conversion + stats
    conv_stats<<<B_ROWS / 8, 256>>>(x, Ws, bs, xh, cb);
    // #1-#3: weight conversions
    conv_w_single<<<(512 * 384 + 255) / 256, 256>>>(W1, 365, 512, 384, w1);
    conv_w_single<<<(256 * 512 + 255) / 256, 256>>>(W2, 512, 256, 512, w2);
    conv_w_rest<<<(128*256 + 64*192 + 32*64 + 255) / 256, 256>>>(W3, w3, Wc1, w4, Wc2, w5);

    // #4: gemm1 [65536,384]x[384,512], 128x256 tiles (profiled)
    gemm_mma<256, 6, 1, false><<<dim3(2, B_ROWS / 128), 256, SM256>>>(
        xh, w1, b1, h1, nullptr, 512);
    // #5: gemm2 [65536,512]x[512,256], 128x256 tiles, grid.x=1
    gemm_mma<256, 8, 1, false><<<dim3(1, B_ROWS / 128), 256, SM256>>>(
        h1, w2, b2, h2, nullptr, 256);
    // #6: gemm3 -> cb[:,0:128]
    gemm_mma<128, 4, 2, false><<<dim3(1, B_ROWS / 128), 256, SM128>>>(
        h2, w3, b3, cb, nullptr, 192);
    // #7: gemm4 [65536,192]x[192,64]
    gemm_mma<64, 3, 2, false><<<dim3(1, B_ROWS / 128), 256, SM64>>>(
        cb, w4, bc1, c1, nullptr, 64);
    // #8: gemm5 [65536,64]x[64,32] -> fp32 c2
    gemm_mma<32, 1, 2, true><<<dim3(1, B_ROWS / 128), 256, SM32>>>(
        c1, w5, bc2, nullptr, c2, 32);
    // #9: head
    head_final<<<B_ROWS / 8, 256>>>(c2, Wc3, bc3, out);
}

// round 6
// speedup vs baseline: 1.1811x; 1.1811x over previous
#include <cuda_runtime.h>
#include <cuda_fp16.h>
#include <math.h>
#include <stdint.h>

#define B_ROWS 65536
#define T_DIM  365

// ---------------------------------------------------------------------------
// Scratch (device globals)
// ---------------------------------------------------------------------------
__device__ half g_x  [(size_t)B_ROWS * 384];
__device__ half g_h1 [(size_t)B_ROWS * 512];
__device__ half g_h2 [(size_t)B_ROWS * 256];
__device__ half g_cb [(size_t)B_ROWS * 192];   // [h3(128) | stats(32) | zero(32)]
// weights transposed to [N, Kpad] fp16
__device__ half g_w1[512*384];
__device__ half g_w2[256*512];
__device__ half g_w3[128*256];
__device__ half g_w4[64*192];
__device__ half g_w5[32*64];

// ---------------------------------------------------------------------------
// Baseline-PTX helpers (sm_80+; assemble on plain sm_103)
// ---------------------------------------------------------------------------
__device__ __forceinline__ uint32_t smem_u32(const void* p) {
    uint32_t a;
    asm("{ .reg .u64 t; cvta.to.shared.u64 t, %1; cvt.u32.u64 %0, t; }" : "=r"(a) : "l"(p));
    return a;
}
__device__ __forceinline__ void cpa16(uint32_t dst, const void* src) {
    asm volatile("cp.async.cg.shared.global [%0], [%1], 16;" :: "r"(dst), "l"(src));
}
#define CP_COMMIT() asm volatile("cp.async.commit_group;" ::: "memory")
template<int N>
__device__ __forceinline__ void cp_wait() {
    asm volatile("cp.async.wait_group %0;" :: "n"(N) : "memory");
}
#define LDM4(r, addr) \
    asm volatile("ldmatrix.sync.aligned.m8n8.x4.shared.b16 {%0,%1,%2,%3}, [%4];" \
        : "=r"((r)[0]), "=r"((r)[1]), "=r"((r)[2]), "=r"((r)[3]) : "r"(addr))
#define MMA_F16(d, a, b0, b1) \
    asm volatile("mma.sync.aligned.m16n8k16.row.col.f32.f16.f16.f32 " \
        "{%0,%1,%2,%3}, {%4,%5,%6,%7}, {%8,%9}, {%0,%1,%2,%3};" \
        : "+f"((d)[0]), "+f"((d)[1]), "+f"((d)[2]), "+f"((d)[3]) \
        : "r"((a)[0]), "r"((a)[1]), "r"((a)[2]), "r"((a)[3]), \
          "r"(b0), "r"(b1))

// ---------------------------------------------------------------------------
// fp16 mma.sync GEMM: out[128 x NT] = relu(A @ W^T + bias)   (round-4 proven)
// k-chunk 64 (128B rows, 8x16B granules, XOR-(r&7) swizzle).
// 3-stage cp.async pipeline; 8 warps = 4m x 2n (warp tile 32 x NT/2).
// ---------------------------------------------------------------------------
template<int NT, int NC>
__global__ void __launch_bounds__(256, 2)
gemm_mma(const half* __restrict__ A, const half* __restrict__ W,
         const float* __restrict__ bias, half* __restrict__ Oh, int ldc)
{
    constexpr int KPAD   = NC * 64;
    constexpr int WN     = NT / 2;
    constexpr int NB     = WN / 16;
    constexpr int NF     = WN / 8;
    constexpr int ABYTES = 128 * 128;
    constexpr int BBYTES = NT * 128;
    constexpr int STAGE  = ABYTES + BBYTES;

    extern __shared__ __align__(1024) char sm[];
    const uint32_t sb = smem_u32(sm);

    const int tid  = threadIdx.x;
    const int wid  = tid >> 5;
    const int lane = tid & 31;
    const int m0   = blockIdx.y * 128;
    const int n0   = blockIdx.x * NT;
    const int wm   = (wid >> 1) * 32;
    const int wn   = (wid & 1) * WN;

    float acc[2][NF][4];
    #pragma unroll
    for (int i = 0; i < 2; i++)
        #pragma unroll
        for (int j = 0; j < NF; j++)
            #pragma unroll
            for (int q = 0; q < 4; q++) acc[i][j][q] = 0.0f;

    auto stage = [&](int c) {
        const uint32_t sA = sb + (c % 3) * STAGE;
        const uint32_t sB = sA + ABYTES;
        #pragma unroll
        for (int i = tid; i < 1024; i += 256) {
            int r = i >> 3, cc = i & 7;
            cpa16(sA + r * 128 + ((cc ^ (r & 7)) << 4),
                  A + (size_t)(m0 + r) * KPAD + c * 64 + cc * 8);
        }
        #pragma unroll
        for (int i = tid; i < NT * 8; i += 256) {
            int r = i >> 3, cc = i & 7;
            cpa16(sB + r * 128 + ((cc ^ (r & 7)) << 4),
                  W + (size_t)(n0 + r) * KPAD + c * 64 + cc * 8);
        }
        CP_COMMIT();
    };

    stage(0);
    if (NC > 1) stage(1);

    for (int c = 0; c < NC; ++c) {
        if (c + 2 < NC)      { stage(c + 2); cp_wait<2>(); }
        else if (c + 1 < NC) { cp_wait<1>(); }
        else                 { cp_wait<0>(); }
        __syncthreads();

        const uint32_t sA = sb + (c % 3) * STAGE;
        const uint32_t sB = sA + ABYTES;

        #pragma unroll
        for (int ks = 0; ks < 4; ++ks) {
            const int g = ks * 2 + (lane >> 4);
            uint32_t a[2][4];
            #pragma unroll
            for (int mi = 0; mi < 2; ++mi) {
                int row = wm + mi * 16 + (lane & 15);
                LDM4(a[mi], sA + row * 128 + ((g ^ (row & 7)) << 4));
            }
            #pragma unroll
            for (int nb = 0; nb < NB; ++nb) {
                int row = wn + nb * 16 + (lane & 15);
                uint32_t t[4];
                LDM4(t, sB + row * 128 + ((g ^ (row & 7)) << 4));
                #pragma unroll
                for (int mi = 0; mi < 2; ++mi) {
                    MMA_F16(acc[mi][2*nb],   a[mi], t[0], t[2]);
                    MMA_F16(acc[mi][2*nb+1], a[mi], t[1], t[3]);
                }
            }
        }
        __syncthreads();
    }

    #pragma unroll
    for (int mi = 0; mi < 2; ++mi) {
        #pragma unroll
        for (int nf = 0; nf < NF; ++nf) {
            int r0 = m0 + wm + mi * 16 + (lane >> 2);
            int cb = n0 + wn + nf * 8 + (lane & 3) * 2;
            float bia0 = bias[cb], bia1 = bias[cb + 1];
            #pragma unroll
            for (int h = 0; h < 2; ++h) {
                int r = r0 + h * 8;
                float v0 = fmaxf(acc[mi][nf][h * 2]     + bia0, 0.0f);
                float v1 = fmaxf(acc[mi][nf][h * 2 + 1] + bia1, 0.0f);
                *(__half2*)(Oh + (size_t)r * ldc + cb) = __floats2half2_rn(v0, v1);
            }
        }
    }
}

// ---------------------------------------------------------------------------
// Fused tail: c1 = relu(cb@W4^T+bc1); c2 = relu(c1@W5^T+bc2);
//             out = sigmoid(c2@Wc3+bc3)*4+6.   One CTA per 128 rows.
// smem layout (dynamic):
//   [0, 48K)       A tile  (128 rows x 3 chunks x 128B, swizzled)
//   [48K, 72K)     W4      (64 rows x 3 chunks x 128B)
//   [72K, 76K)     W5      (32 rows x 1 chunk x 128B)
//   [76K, 92K)     C1      (128 rows x 1 chunk x 128B, fp16 swizzled)
//   [92K, ...)     C2      (float [128][33], padded vs bank conflicts)
// ---------------------------------------------------------------------------
__global__ void __launch_bounds__(256, 1)
fused_tail(const half* __restrict__ cbg, const half* __restrict__ W4,
           const half* __restrict__ W5,
           const float* __restrict__ bc1, const float* __restrict__ bc2,
           const float* __restrict__ Wc3, const float* __restrict__ bc3,
           float* __restrict__ out)
{
    constexpr int SA  = 0;
    constexpr int SW4 = 49152;
    constexpr int SW5 = SW4 + 24576;
    constexpr int SC1 = SW5 + 4096;
    constexpr int SC2 = SC1 + 16384;        // float [128][33]

    extern __shared__ __align__(1024) char sm[];
    const uint32_t sb = smem_u32(sm);
    float* c2s = (float*)(sm + SC2);

    const int tid  = threadIdx.x;
    const int wid  = tid >> 5;
    const int lane = tid & 31;
    const int m0   = blockIdx.x * 128;
    const int wm   = (wid >> 1) * 32;

    // ---- single-shot staging: A(48K) + W4(24K) + W5(4K) ----
    #pragma unroll
    for (int i = tid; i < 128 * 3 * 8; i += 256) {       // A: row, chunk, granule
        int r = (i >> 3) & 127, c = i >> 10, cc = i & 7;
        cpa16(sb + SA + c * 16384 + r * 128 + ((cc ^ (r & 7)) << 4),
              cbg + (size_t)(m0 + r) * 192 + c * 64 + cc * 8);
    }
    #pragma unroll
    for (int i = tid; i < 64 * 3 * 8; i += 256) {        // W4
        int r = (i >> 3) & 63, c = i >> 9, cc = i & 7;
        cpa16(sb + SW4 + c * 8192 + r * 128 + ((cc ^ (r & 7)) << 4),
              W4 + (size_t)r * 192 + c * 64 + cc * 8);
    }
    {
        int i = tid;
        if (i < 32 * 8) {                                // W5
            int r = i >> 3, cc = i & 7;
            cpa16(sb + SW5 + r * 128 + ((cc ^ (r & 7)) << 4),
                  W5 + (size_t)r * 64 + cc * 8);
        }
    }
    CP_COMMIT();
    cp_wait<0>();
    __syncthreads();

    // ---- L4: c1[128x64] = relu(A @ W4^T + bc1), 8 warps 4m x 2n (WN=32) ----
    {
        const int wn = (wid & 1) * 32;
        float acc[2][4][4];
        #pragma unroll
        for (int i = 0; i < 2; i++)
            #pragma unroll
            for (int j = 0; j < 4; j++)
                #pragma unroll
                for (int q = 0; q < 4; q++) acc[i][j][q] = 0.0f;

        #pragma unroll
        for (int c = 0; c < 3; ++c) {
            #pragma unroll
            for (int ks = 0; ks < 4; ++ks) {
                const int g = ks * 2 + (lane >> 4);
                uint32_t a[2][4];
                #pragma unroll
                for (int mi = 0; mi < 2; ++mi) {
                    int row = wm + mi * 16 + (lane & 15);
                    LDM4(a[mi], sb + SA + c * 16384 + row * 128 + ((g ^ (row & 7)) << 4));
                }
                #pragma unroll
                for (int nb = 0; nb < 2; ++nb) {
                    int row = wn + nb * 16 + (lane & 15);
                    uint32_t t[4];
                    LDM4(t, sb + SW4 + c * 8192 + row * 128 + ((g ^ (row & 7)) << 4));
                    #pragma unroll
                    for (int mi = 0; mi < 2; ++mi) {
                        MMA_F16(acc[mi][2*nb],   a[mi], t[0], t[2]);
                        MMA_F16(acc[mi][2*nb+1], a[mi], t[1], t[3]);
                    }
                }
            }
        }
        // epilogue -> C1 smem (fp16, swizzled 128B rows)
        #pragma unroll
        for (int mi = 0; mi < 2; ++mi) {
            #pragma unroll
            for (int nf = 0; nf < 4; ++nf) {
                int r0 = wm + mi * 16 + (lane >> 2);
                int cc = wn + nf * 8 + (lane & 3) * 2;
                float bia0 = bc1[cc], bia1 = bc1[cc + 1];
                int g = cc >> 3, off = (cc & 7) * 2;
                #pragma unroll
                for (int h = 0; h < 2; ++h) {
                    int r = r0 + h * 8;
                    __half2 hv = __floats2half2_rn(
                        fmaxf(acc[mi][nf][h * 2]     + bia0, 0.0f),
                        fmaxf(acc[mi][nf][h * 2 + 1] + bia1, 0.0f));
                    *(__half2*)(sm + SC1 + r * 128 + ((g ^ (r & 7)) << 4) + off) = hv;
                }
            }
        }
    }
    __syncthreads();

    // ---- L5: c2[128x32] = relu(C1 @ W5^T + bc2), WN=16 ----
    {
        const int wn = (wid & 1) * 16;
        float acc[2][2][4];
        #pragma unroll
        for (int i = 0; i < 2; i++)
            #pragma unroll
            for (int j = 0; j < 2; j++)
                #pragma unroll
                for (int q = 0; q < 4; q++) acc[i][j][q] = 0.0f;

        #pragma unroll
        for (int ks = 0; ks < 4; ++ks) {
            const int g = ks * 2 + (lane >> 4);
            uint32_t a[2][4];
            #pragma unroll
            for (int mi = 0; mi < 2; ++mi) {
                int row = wm + mi * 16 + (lane & 15);
                LDM4(a[mi], sb + SC1 + row * 128 + ((g ^ (row & 7)) << 4));
            }
            int row = wn + (lane & 15);
            uint32_t t[4];
            LDM4(t, sb + SW5 + row * 128 + ((g ^ (row & 7)) << 4));
            #pragma unroll
            for (int mi = 0; mi < 2; ++mi) {
                MMA_F16(acc[mi][0], a[mi], t[0], t[2]);
                MMA_F16(acc[mi][1], a[mi], t[1], t[3]);
            }
        }
        #pragma unroll
        for (int mi = 0; mi < 2; ++mi) {
            #pragma unroll
            for (int nf = 0; nf < 2; ++nf) {
                int r0 = wm + mi * 16 + (lane >> 2);
                int cc = wn + nf * 8 + (lane & 3) * 2;
                float bia0 = bc2[cc], bia1 = bc2[cc + 1];
                #pragma unroll
                for (int h = 0; h < 2; ++h) {
                    int r = r0 + h * 8;
                    c2s[r * 33 + cc]     = fmaxf(acc[mi][nf][h * 2]     + bia0, 0.0f);
                    c2s[r * 33 + cc + 1] = fmaxf(acc[mi][nf][h * 2 + 1] + bia1, 0.0f);
                }
            }
        }
    }
    __syncthreads();

    // ---- head: one thread per row ----
    if (tid < 128) {
        float s = bc3[0];
        #pragma unroll
        for (int j = 0; j < 32; ++j) s = fmaf(c2s[tid * 33 + j], Wc3[j], s);
        out[m0 + tid] = 4.0f / (1.0f + expf(-s)) + 6.0f;
    }
}

// ---------------------------------------------------------------------------
// Fused: x -> fp16 (padded to 384) + per-row stats + 6->32 projection.
// ---------------------------------------------------------------------------
__global__ void conv_stats(const float* __restrict__ x,
                           const float* __restrict__ Ws,
                           const float* __restrict__ bs,
                           half* __restrict__ xh, half* __restrict__ cb)
{
    int gwarp = (blockIdx.x * blockDim.x + threadIdx.x) >> 5;
    int lane  = threadIdx.x & 31;
    if (gwarp >= B_ROWS) return;

    const float* row = x + (size_t)gwarp * T_DIM;
    constexpr int NV = 12;
    float v[NV];
    float sum = 0.0f, mn = INFINITY, mx = -INFINITY;
    #pragma unroll
    for (int i = 0; i < NV; i++) {
        int k = lane + 32 * i;
        float t = (k < T_DIM) ? row[k] : 0.0f;
        v[i] = t;
        if (k < T_DIM) { sum += t; mn = fminf(mn, t); mx = fmaxf(mx, t); }
    }
    half* xr = xh + (size_t)gwarp * 384;
    #pragma unroll
    for (int i = 0; i < NV; i++) xr[lane + 32 * i] = __float2half_rn(v[i]);

    #pragma unroll
    for (int off = 16; off; off >>= 1) {
        sum += __shfl_xor_sync(0xffffffffu, sum, off);
        mn   = fminf(mn, __shfl_xor_sync(0xffffffffu, mn, off));
        mx   = fmaxf(mx, __shfl_xor_sync(0xffffffffu, mx, off));
    }
    float mean = sum / (float)T_DIM;
    float s2 = 0.0f, s3 = 0.0f, s4 = 0.0f;
    #pragma unroll
    for (int i = 0; i < NV; i++) {
        int k = lane + 32 * i;
        if (k < T_DIM) {
            float c  = v[i] - mean;
            float c2 = c * c;
            s2 += c2; s3 += c2 * c; s4 += c2 * c2;
        }
    }
    #pragma unroll
    for (int off = 16; off; off >>= 1) {
        s2 += __shfl_xor_sync(0xffffffffu, s2, off);
        s3 += __shfl_xor_sync(0xffffffffu, s3, off);
        s4 += __shfl_xor_sync(0xffffffffu, s4, off);
    }
    float var  = s2 / (float)(T_DIM - 1);
    float sd   = sqrtf(var);
    float skew = (s3 / (float)T_DIM) / (sd * sd * sd + 1e-8f);
    float kurt = (s4 / (float)T_DIM) / (var * var + 1e-8f);

    float st[6] = { mean, sd, mn, mx, skew, kurt };
    float o = bs[lane];
    #pragma unroll
    for (int i = 0; i < 6; i++) o = fmaf(st[i], Ws[i * 32 + lane], o);

    size_t base = (size_t)gwarp * 192;
    cb[base + 128 + lane] = __float2half_rn(o);
    cb[base + 160 + lane] = __float2half_rn(0.0f);
}

// W [K,N] fp32 -> Wt [N,Kpad] fp16 (transposed + zero-padded)
__device__ __forceinline__ void conv_one(const float* W, int K, int N, int Kpad,
                                         half* o, int i) {
    int n = i / Kpad, kp = i % Kpad;
    o[i] = __float2half_rn((kp < K) ? W[(size_t)kp * N + n] : 0.0f);
}
__global__ void conv_w12(const float* __restrict__ W1, half* __restrict__ w1,
                         const float* __restrict__ W2, half* __restrict__ w2) {
    int i = blockIdx.x * blockDim.x + threadIdx.x;
    if (i < 512 * 384)                conv_one(W1, 365, 512, 384, w1, i);
    else if (i < 512*384 + 256*512)   conv_one(W2, 512, 256, 512, w2, i - 512*384);
}
__global__ void conv_w_rest(const float* __restrict__ W3,  half* __restrict__ w3,
                            const float* __restrict__ Wc1, half* __restrict__ w4,
                            const float* __restrict__ Wc2, half* __restrict__ w5) {
    int i = blockIdx.x * blockDim.x + threadIdx.x;
    if (i < 128 * 256)                 conv_one(W3, 256, 128, 256, w3, i);
    else if (i < 128*256 + 64*192)     conv_one(Wc1, 160, 64, 192, w4, i - 128*256);
    else if (i < 128*256 + 64*192 + 32*64)
                                       conv_one(Wc2, 64, 32, 64, w5, i - 128*256 - 64*192);
}

// ---------------------------------------------------------------------------
// Launch  (index 3 = gemm1: profiler has landed on the 4th launch in r3-r5)
// ---------------------------------------------------------------------------
extern "C" void kernel_launch(void* const* d_in, const int* in_sizes, int n_in,
                              void* d_out, int out_size)
{
    const float* x   = (const float*)d_in[0];
    const float* W1  = (const float*)d_in[1];
    const float* b1  = (const float*)d_in[2];
    const float* W2  = (const float*)d_in[3];
    const float* b2  = (const float*)d_in[4];
    const float* W3  = (const float*)d_in[5];
    const float* b3  = (const float*)d_in[6];
    const float* Ws  = (const float*)d_in[7];
    const float* bs  = (const float*)d_in[8];
    const float* Wc1 = (const float*)d_in[9];
    const float* bc1 = (const float*)d_in[10];
    const float* Wc2 = (const float*)d_in[11];
    const float* bc2 = (const float*)d_in[12];
    const float* Wc3 = (const float*)d_in[13];
    const float* bc3 = (const float*)d_in[14];
    float* out = (float*)d_out;

    half *xh, *h1, *h2, *cb, *w1, *w2, *w3, *w4, *w5;
    cudaGetSymbolAddress((void**)&xh, g_x);
    cudaGetSymbolAddress((void**)&h1, g_h1);
    cudaGetSymbolAddress((void**)&h2, g_h2);
    cudaGetSymbolAddress((void**)&cb, g_cb);
    cudaGetSymbolAddress((void**)&w1, g_w1);
    cudaGetSymbolAddress((void**)&w2, g_w2);
    cudaGetSymbolAddress((void**)&w3, g_w3);
    cudaGetSymbolAddress((void**)&w4, g_w4);
    cudaGetSymbolAddress((void**)&w5, g_w5);

    const int SM128 = 3 * (16384 + 128 * 128);            // 98304
    const int SMTAIL = 49152 + 24576 + 4096 + 16384 + 128 * 33 * 4; // 111104
    cudaFuncSetAttribute(gemm_mma<128, 6>, cudaFuncAttributeMaxDynamicSharedMemorySize, SM128);
    cudaFuncSetAttribute(gemm_mma<128, 8>, cudaFuncAttributeMaxDynamicSharedMemorySize, SM128);
    cudaFuncSetAttribute(gemm_mma<128, 4>, cudaFuncAttributeMaxDynamicSharedMemorySize, SM128);
    cudaFuncSetAttribute(fused_tail,       cudaFuncAttributeMaxDynamicSharedMemorySize, SMTAIL);

    // #0: fused x-conversion + stats
    conv_stats<<<B_ROWS / 8, 256>>>(x, Ws, bs, xh, cb);
    // #1-#2: weight conversions
    conv_w12<<<(512*384 + 256*512 + 255) / 256, 256>>>(W1, w1, W2, w2);
    conv_w_rest<<<(128*256 + 64*192 + 32*64 + 255) / 256, 256>>>(W3, w3, Wc1, w4, Wc2, w5);

    // #3: gemm1 [65536,384]x[384,512]  (profiled)
    gemm_mma<128, 6><<<dim3(4, B_ROWS / 128), 256, SM128>>>(xh, w1, b1, h1, 512);
    // #4: gemm2 [65536,512]x[512,256]
    gemm_mma<128, 8><<<dim3(2, B_ROWS / 128), 256, SM128>>>(h1, w2, b2, h2, 256);
    // #5: gemm3 [65536,256]x[256,128] -> cb[:,0:128]
    gemm_mma<128, 4><<<dim3(1, B_ROWS / 128), 256, SM128>>>(h2, w3, b3, cb, 192);
    // #6: fused layers 4+5+head
    fused_tail<<<B_ROWS / 128, 256, SMTAIL>>>(cb, w4, w5, bc1, bc2, Wc3, bc3, out);
}